// round 4
// baseline (speedup 1.0000x reference)
#include <cuda_runtime.h>

// AbstractRelu (DeepPoly ReLU relaxation), elementwise over N fp32.
// out layout: [relu(x) (N)] [lb_slope*low (N)] [relu(high) (N)]
//
// R4: persistent grid (148 SMs x 8 CTAs = 1184 blocks) with a grid-stride
// loop. Loads stay SEQUENTIAL per iteration (MLP_p1=3, avoiding the R2
// front-batch L1tex-queue regression); the scoreboard overlaps iter k's
// stores with iter k+1's loads. Removes ~13 wave transitions of the
// R1 16384-block launch. Streaming hints kept (neutral, not harmful).

#define PERSISTENT_BLOCKS (148 * 8)

__global__ void __launch_bounds__(256, 8)
abstract_relu_kernel(const float4* __restrict__ x,
                     const float4* __restrict__ low,
                     const float4* __restrict__ high,
                     float4* __restrict__ x_out,
                     float4* __restrict__ low_out,
                     float4* __restrict__ high_out,
                     int n4)
{
    const int stride = blockDim.x * gridDim.x;   // 303104
    int i = blockIdx.x * blockDim.x + threadIdx.x;

    for (; i < n4; i += stride) {
        float4 xv = __ldcs(&x[i]);
        float4 lv = __ldcs(&low[i]);
        float4 hv = __ldcs(&high[i]);

        float4 xo, lo, ho;

        #define LANE(f)                                                    \
        {                                                                  \
            float xe = xv.f, le = lv.f, he = hv.f;                         \
            xo.f = fmaxf(xe, 0.0f);                                        \
            ho.f = fmaxf(he, 0.0f);                                        \
            bool zero = (he <= 0.0f) || (le < 0.0f && le * le > he * he);  \
            lo.f = zero ? 0.0f : le;                                       \
        }

        LANE(x) LANE(y) LANE(z) LANE(w)
        #undef LANE

        __stcs(&x_out[i],    xo);
        __stcs(&low_out[i],  lo);
        __stcs(&high_out[i], ho);
    }
}

extern "C" void kernel_launch(void* const* d_in, const int* in_sizes, int n_in,
                              void* d_out, int out_size)
{
    const float* x    = (const float*)d_in[0];
    const float* low  = (const float*)d_in[1];
    const float* high = (const float*)d_in[2];
    float* out = (float*)d_out;

    const int n  = in_sizes[0];          // 16777216
    const int n4 = n / 4;                // 4194304

    float* x_out    = out;
    float* low_out  = out + n;
    float* high_out = out + 2 * (size_t)n;

    abstract_relu_kernel<<<PERSISTENT_BLOCKS, 256>>>(
        (const float4*)x, (const float4*)low, (const float4*)high,
        (float4*)x_out, (float4*)low_out, (float4*)high_out, n4);
}

// round 5
// speedup vs baseline: 1.1340x; 1.1340x over previous
#include <cuda_runtime.h>

// AbstractRelu (DeepPoly ReLU relaxation), elementwise over N fp32.
// out layout: [relu(x) (N)] [lb_slope*low (N)] [relu(high) (N)]
//
// R5: R3 structure (1 float4 quad/thread, sequential loads, MLP_p1=3,
// streaming hints) with block size 128 instead of 256 (grid 32768).
// Finer CTA granularity for wave-tail balance; all else identical.
// Prior results: R1/R3 (256t) 63.6us; R2 front-batch 65.6us (regressed);
// R4 persistent 71.7us (regressed).

__global__ void __launch_bounds__(128, 16)
abstract_relu_kernel(const float4* __restrict__ x,
                     const float4* __restrict__ low,
                     const float4* __restrict__ high,
                     float4* __restrict__ x_out,
                     float4* __restrict__ low_out,
                     float4* __restrict__ high_out,
                     int n4)
{
    int i = blockIdx.x * blockDim.x + threadIdx.x;
    if (i >= n4) return;

    float4 xv = __ldcs(&x[i]);
    float4 lv = __ldcs(&low[i]);
    float4 hv = __ldcs(&high[i]);

    float4 xo, lo, ho;

    #define LANE(f)                                                        \
    {                                                                      \
        float xe = xv.f, le = lv.f, he = hv.f;                             \
        xo.f = fmaxf(xe, 0.0f);                                            \
        ho.f = fmaxf(he, 0.0f);                                            \
        bool zero = (he <= 0.0f) || (le < 0.0f && le * le > he * he);      \
        lo.f = zero ? 0.0f : le;                                           \
    }

    LANE(x) LANE(y) LANE(z) LANE(w)
    #undef LANE

    __stcs(&x_out[i],    xo);
    __stcs(&low_out[i],  lo);
    __stcs(&high_out[i], ho);
}

extern "C" void kernel_launch(void* const* d_in, const int* in_sizes, int n_in,
                              void* d_out, int out_size)
{
    const float* x    = (const float*)d_in[0];
    const float* low  = (const float*)d_in[1];
    const float* high = (const float*)d_in[2];
    float* out = (float*)d_out;

    const int n  = in_sizes[0];          // 16777216
    const int n4 = n / 4;                // 4194304

    float* x_out    = out;
    float* low_out  = out + n;
    float* high_out = out + 2 * (size_t)n;

    const int threads = 128;
    const int blocks  = (n4 + threads - 1) / threads;  // 32768

    abstract_relu_kernel<<<blocks, threads>>>(
        (const float4*)x, (const float4*)low, (const float4*)high,
        (float4*)x_out, (float4*)low_out, (float4*)high_out, n4);
}